// round 14
// baseline (speedup 1.0000x reference)
#include <cuda_runtime.h>
#include <cuda_bf16.h>
#include <cstdint>

#define Hh 320
#define Ww 320
#define HWp 102400
#define Bb 8
#define NBLK 64

// ---------------- scratch (device globals: no allocation allowed) ----------------
__device__ float g_t1[(size_t)Bb*32*HWp];
__device__ float g_t1b[(size_t)Bb*32*HWp];
__device__ float g_t2[(size_t)Bb*8*HWp];
__device__ float g_guid[(size_t)Bb*8*HWp];
__device__ float g_fus[(size_t)Bb*HWp];
__device__ float g_t5[(size_t)Bb*24*HWp];
__device__ float g_oa[(size_t)Bb*24*HWp];
__device__ float g_part[32*NBLK*2];
__device__ float g_part2[32*NBLK*2];
__device__ float g_ss[64];
__device__ float g_ss2[64];
__device__ float g_pool[Bb*32];
__device__ float g_gk[Bb*8];
__device__ __align__(16) unsigned char g_wprep[544000];

// ---------------- helpers ----------------
__device__ __forceinline__ uint16_t f2bf(float v) {
    __nv_bfloat16 h = __float2bfloat16_rn(v);
    return *reinterpret_cast<uint16_t*>(&h);
}
__device__ __forceinline__ float bf2f(uint16_t b) {
    __nv_bfloat16 h = *reinterpret_cast<__nv_bfloat16*>(&b);
    return __bfloat162float(h);
}
__device__ __forceinline__ void mma16816(float* c, uint4 a, uint32_t b0, uint32_t b1) {
    asm volatile("mma.sync.aligned.m16n8k16.row.col.f32.bf16.bf16.f32 "
        "{%0,%1,%2,%3}, {%4,%5,%6,%7}, {%8,%9}, {%0,%1,%2,%3};"
        : "+f"(c[0]), "+f"(c[1]), "+f"(c[2]), "+f"(c[3])
        : "r"(a.x), "r"(a.y), "r"(a.z), "r"(a.w), "r"(b0), "r"(b1));
}

// ---------------- weight prep: pack A fragments ----------------
__global__ void prep_k(const float* __restrict__ w, uint4* __restrict__ dst,
                       int KS2, int CIN, int COUT)
{
    int CH0 = (2*CIN + 15) / 16, CH1 = (CIN + 15) / 16, NCH = CH0 + CH1;
    int MT = (COUT + 15) / 16;
    int idx = blockIdx.x * 256 + threadIdx.x;
    int total = MT * NCH * KS2 * 32;
    if (idx >= total) return;
    int lane = idx & 31;
    int rest = idx >> 5;
    int tap = rest % KS2; rest /= KS2;
    int pc = rest % NCH;
    int mt = rest / NCH;
    int g = lane >> 2, t = lane & 3;
    uint32_t av[4];
    for (int h = 0; h < 2; h++) {
        for (int mr = 0; mr < 2; mr++) {
            int m = mt * 16 + g + mr * 8;
            uint32_t pk = 0;
            if (pc < CH0) {
                int ci = pc * 8 + t + 4 * h;
                float v = (m < COUT && ci < CIN) ? w[(size_t)(m * CIN + ci) * KS2 + tap] : 0.f;
                uint16_t hb = f2bf(v);
                pk = (uint32_t)hb | ((uint32_t)hb << 16);
            } else {
                int j = (pc - CH0) * 8 + t + 4 * h;
                int ci0 = 2 * j, ci1 = 2 * j + 1;
                uint16_t l0 = 0, l1 = 0;
                if (m < COUT && ci0 < CIN) {
                    float v = w[(size_t)(m * CIN + ci0) * KS2 + tap];
                    l0 = f2bf(v - bf2f(f2bf(v)));
                }
                if (m < COUT && ci1 < CIN) {
                    float v = w[(size_t)(m * CIN + ci1) * KS2 + tap];
                    l1 = f2bf(v - bf2f(f2bf(v)));
                }
                pk = (uint32_t)l0 | ((uint32_t)l1 << 16);
            }
            av[h * 2 + mr] = pk;
        }
    }
    dst[idx] = make_uint4(av[0], av[1], av[2], av[3]);
}

// ---------------- per-pixel B builder ----------------
template<bool IN_BN, int CIN, int KPW, int CH0, int CH1>
__device__ __forceinline__ void build_px(uint32_t* __restrict__ rp,
                                         const float* __restrict__ src,
                                         bool ok, const float* __restrict__ sss)
{
    uint16_t xhb[CIN];
#pragma unroll
    for (int ci = 0; ci < CIN; ci++) {
        float v = 0.f;
        if (ok) {
            v = __ldg(src + (size_t)ci * HWp);
            if (IN_BN) v = fmaxf(fmaf(v, sss[ci], sss[CIN + ci]), 0.f);
        }
        uint16_t hb = f2bf(v);
        uint16_t lb = f2bf(v - bf2f(hb));
        int j = ci & 7;
        rp[(ci >> 3) * 8 + 2 * (j & 3) + (j >> 2)] = (uint32_t)hb | ((uint32_t)lb << 16);
        xhb[ci] = hb;
    }
#pragma unroll
    for (int j = 0; j < CIN / 2; j++) {
        int jj = j & 7;
        rp[CH0 * 8 + (j >> 3) * 8 + 2 * (jj & 3) + (jj >> 2)] =
            (uint32_t)xhb[2 * j] | ((uint32_t)xhb[2 * j + 1] << 16);
    }
#pragma unroll
    for (int j = CIN / 2; j < CH1 * 8; j++) {
        int jj = j & 7;
        rp[CH0 * 8 + (j >> 3) * 8 + 2 * (jj & 3) + (jj >> 2)] = 0;
    }
}

// ---------------- mma.sync implicit-GEMM conv (flat builds, per-layer YT) ----------------
template<int KS, int CIN, int COUT, int YT, bool IN_BN, bool HAS_BIAS, bool TANH_OUT>
__global__ __launch_bounds__(128) void convmma_k(
    const float* __restrict__ in, const uint4* __restrict__ wfrag,
    const float* __restrict__ bias, const float* __restrict__ ssg,
    float* __restrict__ out)
{
    constexpr int PAD = KS / 2;
    constexpr int RING = KS + 1;
    constexpr int XT = 64;
    constexpr int NPB = XT + KS - 1;
    constexpr int CH0 = (2 * CIN + 15) / 16;
    constexpr int CH1 = (CIN + 15) / 16;
    constexpr int NCH = CH0 + CH1;
    constexpr int KPW = NCH * 8 + 4;          // ≡ 4 (mod 8) -> conflict-free B loads
    constexpr int TAPS = KS * KS;
    constexpr int MT = (COUT + 15) / 16;

    extern __shared__ uint32_t ring[];        // RING * NPB * KPW
    __shared__ float sss[64];

    const int tid = threadIdx.x;
    const int w = tid >> 5, lane = tid & 31;
    const int g = lane >> 2, t = lane & 3;
    const int x0 = blockIdx.x * XT;
    const int yS = blockIdx.y * YT;
    const int b = blockIdx.z;

    if (IN_BN && tid < 2 * CIN) sss[tid] = ssg[tid];
    __syncthreads();

    const float* inb = in + (size_t)b * CIN * HWp;

    // build NR rows starting at yb; all threads flat over (row, px)
    auto buildN = [&](int yb, int NR) {
        for (int i = tid; i < NR * NPB; i += 128) {
            int row = i / NPB, px = i - row * NPB;
            int yin = yb + row;
            int slot = (yin + PAD) % RING;
            int gx = x0 - PAD + px;
            bool ok = (yin >= 0) & (yin < Hh) & (gx >= 0) & (gx < Ww);
            const float* src = inb + (ptrdiff_t)yin * Ww + gx;
            build_px<IN_BN, CIN, KPW, CH0, CH1>(
                ring + (size_t)slot * NPB * KPW + px * KPW, src, ok, sss);
        }
    };

    const int pxb = w * 16;                   // 4 warps x 16 px = XT

    // prologue: rows yS-PAD .. yS+PAD-1
    buildN(yS - PAD, KS - 1);
    __syncthreads();

    for (int i = 0; i < YT; i += 2) {
        const int y = yS + i;
        buildN(y + PAD, 2);
        __syncthreads();

        float c[2][2][MT][4];
#pragma unroll
        for (int r = 0; r < 2; r++)
#pragma unroll
            for (int n = 0; n < 2; n++)
#pragma unroll
                for (int mt = 0; mt < MT; mt++)
#pragma unroll
                    for (int q = 0; q < 4; q++) c[r][n][mt][q] = 0.f;

        for (int ky = 0; ky < KS; ky++) {
            const uint32_t* r0 = ring + (size_t)((y + ky) % RING) * NPB * KPW;
            const uint32_t* r1 = ring + (size_t)((y + 1 + ky) % RING) * NPB * KPW;
            for (int kx = 0; kx < KS; kx++) {
                const uint32_t* b0p = r0 + (pxb + g + kx) * KPW;
                const uint32_t* b1p = r1 + (pxb + g + kx) * KPW;
                const uint4* ap = wfrag + (size_t)(ky * KS + kx) * 32 + lane;
#pragma unroll
                for (int pc = 0; pc < NCH; pc++) {
                    int wo = pc * 8 + 2 * t;
                    uint2 q0 = *(const uint2*)&b0p[wo];
                    uint2 q1 = *(const uint2*)&b0p[wo + 8 * KPW];
                    uint2 q2 = *(const uint2*)&b1p[wo];
                    uint2 q3 = *(const uint2*)&b1p[wo + 8 * KPW];
#pragma unroll
                    for (int mt = 0; mt < MT; mt++) {
                        uint4 a = __ldg(ap + (size_t)(mt * NCH + pc) * TAPS * 32);
                        mma16816(c[0][0][mt], a, q0.x, q0.y);
                        mma16816(c[0][1][mt], a, q1.x, q1.y);
                        mma16816(c[1][0][mt], a, q2.x, q2.y);
                        mma16816(c[1][1][mt], a, q3.x, q3.y);
                    }
                }
            }
        }

        // store: C[g(+8)][2t,2t+1] per n-subtile, rows y, y+1
#pragma unroll
        for (int r = 0; r < 2; r++) {
            int yr = y + r;
#pragma unroll
            for (int n = 0; n < 2; n++) {
                int xo = x0 + pxb + n * 8 + 2 * t;
                if (xo < Ww) {
#pragma unroll
                    for (int mt = 0; mt < MT; mt++) {
#pragma unroll
                        for (int h2 = 0; h2 < 2; h2++) {
                            int co = mt * 16 + g + h2 * 8;
                            if (co < COUT) {
                                float v0 = c[r][n][mt][2 * h2], v1 = c[r][n][mt][2 * h2 + 1];
                                if (HAS_BIAS) { float bv = __ldg(&bias[co]); v0 += bv; v1 += bv; }
                                if (TANH_OUT) { v0 = tanhf(v0); v1 = tanhf(v1); }
                                float2 o2 = make_float2(v0, v1);
                                *(float2*)&out[((size_t)(b * COUT + co)) * HWp + (size_t)yr * Ww + xo] = o2;
                            }
                        }
                    }
                }
            }
        }
        __syncthreads();
    }
}

// ---------------- BN stats (deterministic, no atomics) ----------------
__global__ void stats_k(const float* __restrict__ x, float* __restrict__ part, int C)
{
    const int c = blockIdx.x, blk = blockIdx.y, NB = gridDim.y;
    const int tid = threadIdx.x;
    float s = 0.f, q = 0.f;
    for (int b = 0; b < Bb; b++) {
        const float* p = x + ((size_t)(b * C + c)) * HWp;
        for (int i = blk * 256 + tid; i < HWp; i += NB * 256) {
            float v = p[i]; s += v; q += v * v;
        }
    }
    __shared__ float rs[256], rq[256];
    rs[tid] = s; rq[tid] = q; __syncthreads();
    for (int off = 128; off > 0; off >>= 1) {
        if (tid < off) { rs[tid] += rs[tid + off]; rq[tid] += rq[tid + off]; }
        __syncthreads();
    }
    if (tid == 0) {
        part[(c * NB + blk) * 2]     = rs[0];
        part[(c * NB + blk) * 2 + 1] = rq[0];
    }
}

__global__ void bnfin_k(const float* __restrict__ part, const float* __restrict__ gamma,
                        const float* __restrict__ beta, int C, float* __restrict__ ss)
{
    int c = threadIdx.x;
    if (c >= C) return;
    double s = 0.0, q = 0.0;
    for (int i = 0; i < NBLK; i++) {
        s += part[(c * NBLK + i) * 2];
        q += part[(c * NBLK + i) * 2 + 1];
    }
    const double N = (double)Bb * HWp;
    float mean = (float)(s / N);
    float var  = (float)(q / N) - mean * mean;
    float scl = gamma[c] * rsqrtf(var + 1e-5f);
    ss[c]     = scl;
    ss[C + c] = beta[c] - mean * scl;
}

// ---------------- pool ----------------
__global__ void pool_k(const float* __restrict__ feat, float* __restrict__ p)
{
    const int bc = blockIdx.x;
    const int tid = threadIdx.x;
    const float* src = feat + (size_t)bc * HWp;
    float s = 0.f;
    for (int i = tid; i < HWp; i += 256) s += src[i];
    __shared__ float rs[256];
    rs[tid] = s; __syncthreads();
    for (int off = 128; off > 0; off >>= 1) {
        if (tid < off) rs[tid] += rs[tid + off];
        __syncthreads();
    }
    if (tid == 0) p[bc] = rs[0] * (1.f / (float)HWp);
}

// ---------------- sigma MLP + gaussian window ----------------
__device__ __forceinline__ float celu1(float x) { return x > 0.f ? x : expm1f(x); }

__global__ void mlp_k(const float* __restrict__ p,
                      const float* __restrict__ s1w, const float* __restrict__ s1b,
                      const float* __restrict__ s2w, const float* __restrict__ s2b,
                      const float* __restrict__ s3w, const float* __restrict__ s3b,
                      float* __restrict__ gk)
{
    int b = threadIdx.x;
    if (b >= Bb) return;
    float h1[16];
#pragma unroll
    for (int j = 0; j < 16; j++) {
        float a = s1b[j];
        for (int i = 0; i < 32; i++) a += p[b * 32 + i] * s1w[j * 32 + i];
        h1[j] = celu1(a);
    }
    float h2[16];
#pragma unroll
    for (int j = 0; j < 16; j++) {
        float a = s2b[j];
        for (int i = 0; i < 16; i++) a += h1[i] * s2w[j * 16 + i];
        h2[j] = celu1(a);
    }
    float sg = s3b[0];
    for (int i = 0; i < 16; i++) sg += h2[i] * s3w[i];
    sg = fmaxf(sg, 0.f) + 0.001f;
    sg += 0.2f;
    float e = expf(-1.f / (2.f * sg * sg));
    float d = 2.f * e + 1.f;
    float e1 = e / d, e0 = 1.f / d;
    float w00 = e1 * e1, w01 = e1 * e0;
    gk[b * 8 + 0] = w00; gk[b * 8 + 1] = w01; gk[b * 8 + 2] = w00; gk[b * 8 + 3] = w01;
    gk[b * 8 + 4] = w01; gk[b * 8 + 5] = w00; gk[b * 8 + 6] = w01; gk[b * 8 + 7] = w00;
}

// ---------------- final: affinity normalize + deform conv 1x9 + abs ----------------
__device__ __forceinline__ float bilin(const float* __restrict__ img, float ys, float xs)
{
    float y0f = floorf(ys), x0f = floorf(xs);
    float wy1 = ys - y0f, wx1 = xs - x0f;
    float wy0 = 1.f - wy1, wx0 = 1.f - wx1;
    int y0 = (int)y0f, x0 = (int)x0f;
    float v00 = 0.f, v01 = 0.f, v10 = 0.f, v11 = 0.f;
    bool yi0 = (y0 >= 0) & (y0 < Hh);
    bool yi1 = (y0 + 1 >= 0) & (y0 + 1 < Hh);
    bool xi0 = (x0 >= 0) & (x0 < Ww);
    bool xi1 = (x0 + 1 >= 0) & (x0 + 1 < Ww);
    if (yi0 & xi0) v00 = img[y0 * Ww + x0];
    if (yi0 & xi1) v01 = img[y0 * Ww + x0 + 1];
    if (yi1 & xi0) v10 = img[(y0 + 1) * Ww + x0];
    if (yi1 & xi1) v11 = img[(y0 + 1) * Ww + x0 + 1];
    return wy0 * wx0 * v00 + wy0 * wx1 * v01 + wy1 * wx0 * v10 + wy1 * wx1 * v11;
}

__global__ void final_k(const float* __restrict__ oa, const float* __restrict__ fusion,
                        const float* __restrict__ gk, const float* __restrict__ ascale_p,
                        float* __restrict__ out)
{
    int idx = blockIdx.x * 256 + threadIdx.x;
    if (idx >= Bb * HWp) return;
    int b = idx / HWp;
    int p = idx - b * HWp;
    int y = p / Ww;
    int x = p - y * Ww;

    float inv_as = 1.f / (ascale_p[0] + 1e-5f);

    float o[24];
    const float* ob = oa + (size_t)b * 24 * HWp + p;
#pragma unroll
    for (int c = 0; c < 24; c++) o[c] = ob[(size_t)c * HWp];

    float aff[8]; float s = 0.f;
#pragma unroll
    for (int k = 0; k < 8; k++) {
        float a = tanhf(o[16 + k]) * inv_as + gk[b * 8 + k];
        aff[k] = a;
        s += fabsf(a);
    }
    s += 1e-5f;
    s = fmaxf(s, 1.f);
    float inv = 1.f / s;
    float suma = 0.f;
#pragma unroll
    for (int k = 0; k < 8; k++) { aff[k] *= inv; suma += aff[k]; }
    float aref = 1.f - suma;

    const float* img = fusion + (size_t)b * HWp;
    float res = 0.f;
#pragma unroll
    for (int j = 0; j < 9; j++) {
        float m, dy, dx;
        if (j == 4) { m = aref; dy = 0.f; dx = 0.f; }
        else {
            int k = (j < 4) ? j : j - 1;
            m = aff[k];
            dy = o[2 * k];
            dx = o[2 * k + 1];
        }
        float ys = (float)y + (float)(j / 3 - 1) + dy;
        float xs = (float)x + (float)(j % 3 - 1) + dx;
        res += m * bilin(img, ys, xs);
    }
    out[idx] = fabsf(res);
}

// ---------------- launch ----------------
extern "C" void kernel_launch(void* const* d_in, const int* in_sizes, int n_in,
                              void* d_out, int out_size)
{
    const float* feat    = (const float*)d_in[0];
    const float* g1_w    = (const float*)d_in[1];
    const float* g1_g    = (const float*)d_in[2];
    const float* g1_b    = (const float*)d_in[3];
    const float* g2_w    = (const float*)d_in[4];
    const float* g2_g    = (const float*)d_in[5];
    const float* g2_b    = (const float*)d_in[6];
    const float* g3_w    = (const float*)d_in[7];
    const float* g3_bias = (const float*)d_in[8];
    const float* f1_w    = (const float*)d_in[9];
    const float* f1_g    = (const float*)d_in[10];
    const float* f1_b    = (const float*)d_in[11];
    const float* f2_w    = (const float*)d_in[12];
    const float* f2_bias = (const float*)d_in[13];
    const float* s1_w    = (const float*)d_in[14];
    const float* s1_b    = (const float*)d_in[15];
    const float* s2_w    = (const float*)d_in[16];
    const float* s2_b    = (const float*)d_in[17];
    const float* s3_w    = (const float*)d_in[18];
    const float* s3_b    = (const float*)d_in[19];
    const float* oa1_w   = (const float*)d_in[20];
    const float* oa1_g   = (const float*)d_in[21];
    const float* oa1_b   = (const float*)d_in[22];
    const float* oa2_w   = (const float*)d_in[23];
    const float* oa2_g   = (const float*)d_in[24];
    const float* oa2_b   = (const float*)d_in[25];
    const float* oa3_w   = (const float*)d_in[26];
    const float* oa3_bias= (const float*)d_in[27];
    const float* ascale  = (const float*)d_in[28];

    float *t1, *t1b, *t2, *guid, *fus, *t5, *oa, *part, *part2, *ss, *ss2, *pool, *gk;
    unsigned char* wp;
    cudaGetSymbolAddress((void**)&t1,   g_t1);
    cudaGetSymbolAddress((void**)&t1b,  g_t1b);
    cudaGetSymbolAddress((void**)&t2,   g_t2);
    cudaGetSymbolAddress((void**)&guid, g_guid);
    cudaGetSymbolAddress((void**)&fus,  g_fus);
    cudaGetSymbolAddress((void**)&t5,   g_t5);
    cudaGetSymbolAddress((void**)&oa,   g_oa);
    cudaGetSymbolAddress((void**)&part, g_part);
    cudaGetSymbolAddress((void**)&part2,g_part2);
    cudaGetSymbolAddress((void**)&ss,   g_ss);
    cudaGetSymbolAddress((void**)&ss2,  g_ss2);
    cudaGetSymbolAddress((void**)&pool, g_pool);
    cudaGetSymbolAddress((void**)&gk,   g_gk);
    cudaGetSymbolAddress((void**)&wp,   g_wprep);

    uint4* W_g1  = (uint4*)(wp + 0);
    uint4* W_g2  = (uint4*)(wp + 153600);
    uint4* W_g3  = (uint4*)(wp + 230400);
    uint4* W_f1  = (uint4*)(wp + 256000);
    uint4* W_f2  = (uint4*)(wp + 311296);
    uint4* W_oa1 = (uint4*)(wp + 338944);
    uint4* W_oa2 = (uint4*)(wp + 364544);
    uint4* W_oa3 = (uint4*)(wp + 415744);

    // <KS,CIN,COUT,YT,...>  YT tuned so blocks ≈ 148 * CTAs/SM
    auto C1 = convmma_k<5,32,32,40,false,false,false>;  // g1  (2 CTAs -> 320 blk)
    auto C2 = convmma_k<5,32, 8,40,true ,false,false>;  // g2  (2 CTAs -> 320 blk)
    auto C3 = convmma_k<5, 8, 8,16,true ,true ,false>;  // g3  (6 CTAs -> 800 blk)
    auto C4 = convmma_k<3,32,32,20,false,false,false>;  // f1  (4 CTAs -> 640 blk)
    auto C5 = convmma_k<3,32, 1,20,true ,true ,true >;  // f2
    auto C6 = convmma_k<5, 8, 8,16,false,false,false>;  // oa1
    auto C7 = convmma_k<5, 8,24,16,true ,false,false>;  // oa2
    auto C8 = convmma_k<5,24,24,32,true ,true ,false>;  // oa3 (3 CTAs -> 400 blk)

    const int SM_c32k5 = 6*68*52*4;   // 84864
    const int SM_c8k5  = 6*68*20*4;   // 32640
    const int SM_c32k3 = 4*66*52*4;   // 54912
    const int SM_c24k5 = 6*68*44*4;   // 71808
    cudaFuncSetAttribute(C1, cudaFuncAttributeMaxDynamicSharedMemorySize, SM_c32k5);
    cudaFuncSetAttribute(C2, cudaFuncAttributeMaxDynamicSharedMemorySize, SM_c32k5);
    cudaFuncSetAttribute(C3, cudaFuncAttributeMaxDynamicSharedMemorySize, SM_c8k5);
    cudaFuncSetAttribute(C4, cudaFuncAttributeMaxDynamicSharedMemorySize, SM_c32k3);
    cudaFuncSetAttribute(C5, cudaFuncAttributeMaxDynamicSharedMemorySize, SM_c32k3);
    cudaFuncSetAttribute(C6, cudaFuncAttributeMaxDynamicSharedMemorySize, SM_c8k5);
    cudaFuncSetAttribute(C7, cudaFuncAttributeMaxDynamicSharedMemorySize, SM_c8k5);
    cudaFuncSetAttribute(C8, cudaFuncAttributeMaxDynamicSharedMemorySize, SM_c24k5);

    const dim3 blk(256);
    const dim3 cblk(128);
    const dim3 gx40(5,  8, Bb);      // YT=40
    const dim3 gx32(5, 10, Bb);      // YT=32
    const dim3 gx20(5, 16, Bb);      // YT=20
    const dim3 gx16(5, 20, Bb);      // YT=16

    // ---- single stream; conv at our launch index 3 for ncu capture ----
    prep_k<<<38, 256>>>(g1_w,  W_g1,  25, 32, 32);                      // 0
    prep_k<<<14, 256>>>(f1_w,  W_f1,   9, 32, 32);                      // 1
    C1<<<gx40, cblk, SM_c32k5>>>(feat, W_g1, nullptr, nullptr, t1);     // 2
    C4<<<gx20, cblk, SM_c32k3>>>(feat, W_f1, nullptr, nullptr, t1b);    // 3 <- ncu
    stats_k<<<dim3(32, NBLK), blk>>>(t1, part, 32);
    bnfin_k<<<1, 32>>>(part, g1_g, g1_b, 32, ss);
    prep_k<<<19, 256>>>(g2_w,  W_g2,  25, 32,  8);
    C2<<<gx40, cblk, SM_c32k5>>>(t1, W_g2, nullptr, ss, t2);
    stats_k<<<dim3(8, NBLK), blk>>>(t2, part, 8);
    bnfin_k<<<1, 32>>>(part, g2_g, g2_b, 8, ss);
    prep_k<<< 7, 256>>>(g3_w,  W_g3,  25,  8,  8);
    C3<<<gx16, cblk, SM_c8k5>>>(t2, W_g3, g3_bias, ss, guid);

    // fuse branch tail (f1 output in t1b)
    stats_k<<<dim3(32, NBLK), blk>>>(t1b, part2, 32);
    bnfin_k<<<1, 32>>>(part2, f1_g, f1_b, 32, ss2);
    prep_k<<< 7, 256>>>(f2_w,  W_f2,   9, 32,  1);
    C5<<<gx20, cblk, SM_c32k3>>>(t1b, W_f2, f2_bias, ss2, fus);

    // sigma branch
    pool_k<<<Bb * 32, blk>>>(feat, pool);
    mlp_k<<<1, 32>>>(pool, s1_w, s1_b, s2_w, s2_b, s3_w, s3_b, gk);

    // off/aff branch (reuses t2 + part)
    prep_k<<< 7, 256>>>(oa1_w, W_oa1, 25,  8,  8);
    C6<<<gx16, cblk, SM_c8k5>>>(guid, W_oa1, nullptr, nullptr, t2);
    stats_k<<<dim3(8, NBLK), blk>>>(t2, part, 8);
    bnfin_k<<<1, 32>>>(part, oa1_g, oa1_b, 8, ss);
    prep_k<<<13, 256>>>(oa2_w, W_oa2, 25,  8, 24);
    C7<<<gx16, cblk, SM_c8k5>>>(t2, W_oa2, nullptr, ss, t5);
    stats_k<<<dim3(24, NBLK), blk>>>(t5, part, 24);
    bnfin_k<<<1, 32>>>(part, oa2_g, oa2_b, 24, ss);
    prep_k<<<32, 256>>>(oa3_w, W_oa3, 25, 24, 24);
    C8<<<gx32, cblk, SM_c24k5>>>(t5, W_oa3, oa3_bias, ss, oa);

    // deformable gather
    final_k<<<(Bb * HWp + 255) / 256, blk>>>(oa, fus, gk, ascale, (float*)d_out);
}

// round 16
// speedup vs baseline: 1.2913x; 1.2913x over previous
#include <cuda_runtime.h>
#include <cuda_bf16.h>
#include <cstdint>

#define Hh 320
#define Ww 320
#define HWp 102400
#define Bb 8
#define NBLK 64

// ---------------- scratch (device globals: no allocation allowed) ----------------
__device__ float g_t1[(size_t)Bb*32*HWp];
__device__ float g_t1b[(size_t)Bb*32*HWp];
__device__ float g_t2[(size_t)Bb*8*HWp];
__device__ float g_guid[(size_t)Bb*8*HWp];
__device__ float g_fus[(size_t)Bb*HWp];
__device__ float g_t5[(size_t)Bb*24*HWp];
__device__ float g_oa[(size_t)Bb*24*HWp];
__device__ float g_part[32*NBLK*2];
__device__ float g_part2[32*NBLK*2];
__device__ float g_ss[64];
__device__ float g_ss2[64];
__device__ float g_pool[Bb*32];
__device__ float g_gk[Bb*8];
__device__ __align__(16) unsigned char g_wprep[544000];

// ---------------- helpers ----------------
__device__ __forceinline__ uint16_t f2bf(float v) {
    __nv_bfloat16 h = __float2bfloat16_rn(v);
    return *reinterpret_cast<uint16_t*>(&h);
}
__device__ __forceinline__ float bf2f(uint16_t b) {
    __nv_bfloat16 h = *reinterpret_cast<__nv_bfloat16*>(&b);
    return __bfloat162float(h);
}
__device__ __forceinline__ void mma16816(float* c, uint4 a, uint32_t b0, uint32_t b1) {
    asm volatile("mma.sync.aligned.m16n8k16.row.col.f32.bf16.bf16.f32 "
        "{%0,%1,%2,%3}, {%4,%5,%6,%7}, {%8,%9}, {%0,%1,%2,%3};"
        : "+f"(c[0]), "+f"(c[1]), "+f"(c[2]), "+f"(c[3])
        : "r"(a.x), "r"(a.y), "r"(a.z), "r"(a.w), "r"(b0), "r"(b1));
}

// ---------------- weight prep: pack A fragments ----------------
__global__ void prep_k(const float* __restrict__ w, uint4* __restrict__ dst,
                       int KS2, int CIN, int COUT)
{
    int CH0 = (2*CIN + 15) / 16, CH1 = (CIN + 15) / 16, NCH = CH0 + CH1;
    int MT = (COUT + 15) / 16;
    int idx = blockIdx.x * 256 + threadIdx.x;
    int total = MT * NCH * KS2 * 32;
    if (idx >= total) return;
    int lane = idx & 31;
    int rest = idx >> 5;
    int tap = rest % KS2; rest /= KS2;
    int pc = rest % NCH;
    int mt = rest / NCH;
    int g = lane >> 2, t = lane & 3;
    uint32_t av[4];
    for (int h = 0; h < 2; h++) {
        for (int mr = 0; mr < 2; mr++) {
            int m = mt * 16 + g + mr * 8;
            uint32_t pk = 0;
            if (pc < CH0) {
                int ci = pc * 8 + t + 4 * h;
                float v = (m < COUT && ci < CIN) ? w[(size_t)(m * CIN + ci) * KS2 + tap] : 0.f;
                uint16_t hb = f2bf(v);
                pk = (uint32_t)hb | ((uint32_t)hb << 16);
            } else {
                int j = (pc - CH0) * 8 + t + 4 * h;
                int ci0 = 2 * j, ci1 = 2 * j + 1;
                uint16_t l0 = 0, l1 = 0;
                if (m < COUT && ci0 < CIN) {
                    float v = w[(size_t)(m * CIN + ci0) * KS2 + tap];
                    l0 = f2bf(v - bf2f(f2bf(v)));
                }
                if (m < COUT && ci1 < CIN) {
                    float v = w[(size_t)(m * CIN + ci1) * KS2 + tap];
                    l1 = f2bf(v - bf2f(f2bf(v)));
                }
                pk = (uint32_t)l0 | ((uint32_t)l1 << 16);
            }
            av[h * 2 + mr] = pk;
        }
    }
    dst[idx] = make_uint4(av[0], av[1], av[2], av[3]);
}

// ---------------- per-pixel B builder ----------------
template<bool IN_BN, int CIN, int KPW, int CH0, int CH1>
__device__ __forceinline__ void build_px(uint32_t* __restrict__ rp,
                                         const float* __restrict__ src,
                                         bool ok, const float* __restrict__ sss)
{
    uint16_t xhb[CIN];
#pragma unroll
    for (int ci = 0; ci < CIN; ci++) {
        float v = 0.f;
        if (ok) {
            v = __ldg(src + (size_t)ci * HWp);
            if (IN_BN) v = fmaxf(fmaf(v, sss[ci], sss[CIN + ci]), 0.f);
        }
        uint16_t hb = f2bf(v);
        uint16_t lb = f2bf(v - bf2f(hb));
        int j = ci & 7;
        rp[(ci >> 3) * 8 + 2 * (j & 3) + (j >> 2)] = (uint32_t)hb | ((uint32_t)lb << 16);
        xhb[ci] = hb;
    }
#pragma unroll
    for (int j = 0; j < CIN / 2; j++) {
        int jj = j & 7;
        rp[CH0 * 8 + (j >> 3) * 8 + 2 * (jj & 3) + (jj >> 2)] =
            (uint32_t)xhb[2 * j] | ((uint32_t)xhb[2 * j + 1] << 16);
    }
#pragma unroll
    for (int j = CIN / 2; j < CH1 * 8; j++) {
        int jj = j & 7;
        rp[CH0 * 8 + (j >> 3) * 8 + 2 * (jj & 3) + (jj >> 2)] = 0;
    }
}

// ---------------- mma.sync implicit-GEMM conv (R10/v4 exact: pc double-buffer) ----------------
template<int KS, int CIN, int COUT, bool IN_BN, bool HAS_BIAS, bool TANH_OUT>
__global__ __launch_bounds__(128) void convmma_k(
    const float* __restrict__ in, const uint4* __restrict__ wfrag,
    const float* __restrict__ bias, const float* __restrict__ ssg,
    float* __restrict__ out)
{
    constexpr int PAD = KS / 2;
    constexpr int RING = KS + 1;
    constexpr int XT = 64;
    constexpr int NPB = XT + KS - 1;
    constexpr int CH0 = (2 * CIN + 15) / 16;
    constexpr int CH1 = (CIN + 15) / 16;
    constexpr int NCH = CH0 + CH1;
    constexpr int KPW = NCH * 8 + 4;
    constexpr int TAPS = KS * KS;
    constexpr int YT = 20;
    constexpr int MT = (COUT + 15) / 16;

    extern __shared__ uint32_t ring[];
    __shared__ float sss[64];

    const int tid = threadIdx.x;
    const int w = tid >> 5, lane = tid & 31;
    const int g = lane >> 2, t = lane & 3;
    const int x0 = blockIdx.x * XT;
    const int yS = blockIdx.y * YT;
    const int b = blockIdx.z;

    if (IN_BN && tid < 2 * CIN) sss[tid] = ssg[tid];
    __syncthreads();

    auto build = [&](int yin) {
        int slot = (yin + PAD) % RING;
        if (tid < NPB) {
            int gx = x0 - PAD + tid;
            bool ok = (yin >= 0) & (yin < Hh) & (gx >= 0) & (gx < Ww);
            const float* src = in + (size_t)b * CIN * HWp + (ptrdiff_t)yin * Ww + gx;
            build_px<IN_BN, CIN, KPW, CH0, CH1>(
                ring + (size_t)slot * NPB * KPW + tid * KPW, src, ok, sss);
        }
    };

    const int pxb = w * 16;

    for (int j = 0; j < KS - 1; j++) build(yS - PAD + j);
    __syncthreads();

    for (int i = 0; i < YT; i += 2) {
        const int y = yS + i;
        build(y + PAD);
        build(y + PAD + 1);
        __syncthreads();

        float c[2][2][MT][4];
#pragma unroll
        for (int r = 0; r < 2; r++)
#pragma unroll
            for (int n = 0; n < 2; n++)
#pragma unroll
                for (int mt = 0; mt < MT; mt++)
#pragma unroll
                    for (int q = 0; q < 4; q++) c[r][n][mt][q] = 0.f;

        for (int ky = 0; ky < KS; ky++) {
            const uint32_t* r0 = ring + (size_t)((y + ky) % RING) * NPB * KPW;
            const uint32_t* r1 = ring + (size_t)((y + 1 + ky) % RING) * NPB * KPW;
#pragma unroll
            for (int kx = 0; kx < KS; kx++) {
                const uint32_t* b0p = r0 + (pxb + g + kx) * KPW;
                const uint32_t* b1p = r1 + (pxb + g + kx) * KPW;
                const uint4* ap = wfrag + (size_t)(ky * KS + kx) * 32 + lane;

                uint2 qb[2][4];
                uint4 ab[2][MT];
                {
                    int wo = 2 * t;
                    qb[0][0] = *(const uint2*)&b0p[wo];
                    qb[0][1] = *(const uint2*)&b0p[wo + 8 * KPW];
                    qb[0][2] = *(const uint2*)&b1p[wo];
                    qb[0][3] = *(const uint2*)&b1p[wo + 8 * KPW];
#pragma unroll
                    for (int mt = 0; mt < MT; mt++)
                        ab[0][mt] = __ldg(ap + (size_t)(mt * NCH) * TAPS * 32);
                }
#pragma unroll
                for (int pc = 0; pc < NCH; pc++) {
                    const int cur = pc & 1, nxt = cur ^ 1;
                    if (pc + 1 < NCH) {
                        int wo = (pc + 1) * 8 + 2 * t;
                        qb[nxt][0] = *(const uint2*)&b0p[wo];
                        qb[nxt][1] = *(const uint2*)&b0p[wo + 8 * KPW];
                        qb[nxt][2] = *(const uint2*)&b1p[wo];
                        qb[nxt][3] = *(const uint2*)&b1p[wo + 8 * KPW];
#pragma unroll
                        for (int mt = 0; mt < MT; mt++)
                            ab[nxt][mt] = __ldg(ap + (size_t)(mt * NCH + pc + 1) * TAPS * 32);
                    }
#pragma unroll
                    for (int mt = 0; mt < MT; mt++) {
                        mma16816(c[0][0][mt], ab[cur][mt], qb[cur][0].x, qb[cur][0].y);
                        mma16816(c[0][1][mt], ab[cur][mt], qb[cur][1].x, qb[cur][1].y);
                        mma16816(c[1][0][mt], ab[cur][mt], qb[cur][2].x, qb[cur][2].y);
                        mma16816(c[1][1][mt], ab[cur][mt], qb[cur][3].x, qb[cur][3].y);
                    }
                }
            }
        }

#pragma unroll
        for (int r = 0; r < 2; r++) {
            int yr = y + r;
#pragma unroll
            for (int n = 0; n < 2; n++) {
                int xo = x0 + pxb + n * 8 + 2 * t;
                if (xo < Ww) {
#pragma unroll
                    for (int mt = 0; mt < MT; mt++) {
#pragma unroll
                        for (int h2 = 0; h2 < 2; h2++) {
                            int co = mt * 16 + g + h2 * 8;
                            if (co < COUT) {
                                float v0 = c[r][n][mt][2 * h2], v1 = c[r][n][mt][2 * h2 + 1];
                                if (HAS_BIAS) { float bv = __ldg(&bias[co]); v0 += bv; v1 += bv; }
                                if (TANH_OUT) { v0 = tanhf(v0); v1 = tanhf(v1); }
                                float2 o2 = make_float2(v0, v1);
                                *(float2*)&out[((size_t)(b * COUT + co)) * HWp + (size_t)yr * Ww + xo] = o2;
                            }
                        }
                    }
                }
            }
        }
        __syncthreads();
    }
}

// ---------------- BN stats (deterministic, no atomics) ----------------
__global__ void stats_k(const float* __restrict__ x, float* __restrict__ part, int C)
{
    const int c = blockIdx.x, blk = blockIdx.y, NB = gridDim.y;
    const int tid = threadIdx.x;
    float s = 0.f, q = 0.f;
    for (int b = 0; b < Bb; b++) {
        const float* p = x + ((size_t)(b * C + c)) * HWp;
        for (int i = blk * 256 + tid; i < HWp; i += NB * 256) {
            float v = p[i]; s += v; q += v * v;
        }
    }
    __shared__ float rs[256], rq[256];
    rs[tid] = s; rq[tid] = q; __syncthreads();
    for (int off = 128; off > 0; off >>= 1) {
        if (tid < off) { rs[tid] += rs[tid + off]; rq[tid] += rq[tid + off]; }
        __syncthreads();
    }
    if (tid == 0) {
        part[(c * NB + blk) * 2]     = rs[0];
        part[(c * NB + blk) * 2 + 1] = rq[0];
    }
}

// parallel BN finalize: ONE WARP PER CHANNEL (blockIdx.x = channel), 32 threads.
// Deterministic: lane-strided loads + full shfl tree. No resource risk.
__global__ __launch_bounds__(32) void bnfin_k(
    const float* __restrict__ part, const float* __restrict__ gamma,
    const float* __restrict__ beta, int C, float* __restrict__ ss)
{
    int c = blockIdx.x;
    if (c >= C) return;
    int lane = threadIdx.x;
    double s = 0.0, q = 0.0;
    for (int i = lane; i < NBLK; i += 32) {
        s += part[(c * NBLK + i) * 2];
        q += part[(c * NBLK + i) * 2 + 1];
    }
#pragma unroll
    for (int o = 16; o > 0; o >>= 1) {
        s += __shfl_down_sync(0xffffffffu, s, o);
        q += __shfl_down_sync(0xffffffffu, q, o);
    }
    if (lane == 0) {
        const double N = (double)Bb * HWp;
        float mean = (float)(s / N);
        float var  = (float)(q / N) - mean * mean;
        float scl = gamma[c] * rsqrtf(var + 1e-5f);
        ss[c]     = scl;
        ss[C + c] = beta[c] - mean * scl;
    }
}

// ---------------- pool ----------------
__global__ void pool_k(const float* __restrict__ feat, float* __restrict__ p)
{
    const int bc = blockIdx.x;
    const int tid = threadIdx.x;
    const float* src = feat + (size_t)bc * HWp;
    float s = 0.f;
    for (int i = tid; i < HWp; i += 256) s += src[i];
    __shared__ float rs[256];
    rs[tid] = s; __syncthreads();
    for (int off = 128; off > 0; off >>= 1) {
        if (tid < off) rs[tid] += rs[tid + off];
        __syncthreads();
    }
    if (tid == 0) p[bc] = rs[0] * (1.f / (float)HWp);
}

// ---------------- sigma MLP + gaussian window ----------------
__device__ __forceinline__ float celu1(float x) { return x > 0.f ? x : expm1f(x); }

__global__ void mlp_k(const float* __restrict__ p,
                      const float* __restrict__ s1w, const float* __restrict__ s1b,
                      const float* __restrict__ s2w, const float* __restrict__ s2b,
                      const float* __restrict__ s3w, const float* __restrict__ s3b,
                      float* __restrict__ gk)
{
    int b = threadIdx.x;
    if (b >= Bb) return;
    float h1[16];
#pragma unroll
    for (int j = 0; j < 16; j++) {
        float a = s1b[j];
        for (int i = 0; i < 32; i++) a += p[b * 32 + i] * s1w[j * 32 + i];
        h1[j] = celu1(a);
    }
    float h2[16];
#pragma unroll
    for (int j = 0; j < 16; j++) {
        float a = s2b[j];
        for (int i = 0; i < 16; i++) a += h1[i] * s2w[j * 16 + i];
        h2[j] = celu1(a);
    }
    float sg = s3b[0];
    for (int i = 0; i < 16; i++) sg += h2[i] * s3w[i];
    sg = fmaxf(sg, 0.f) + 0.001f;
    sg += 0.2f;
    float e = expf(-1.f / (2.f * sg * sg));
    float d = 2.f * e + 1.f;
    float e1 = e / d, e0 = 1.f / d;
    float w00 = e1 * e1, w01 = e1 * e0;
    gk[b * 8 + 0] = w00; gk[b * 8 + 1] = w01; gk[b * 8 + 2] = w00; gk[b * 8 + 3] = w01;
    gk[b * 8 + 4] = w01; gk[b * 8 + 5] = w00; gk[b * 8 + 6] = w01; gk[b * 8 + 7] = w00;
}

// ---------------- final: affinity normalize + deform conv 1x9 + abs ----------------
__device__ __forceinline__ float bilin(const float* __restrict__ img, float ys, float xs)
{
    float y0f = floorf(ys), x0f = floorf(xs);
    float wy1 = ys - y0f, wx1 = xs - x0f;
    float wy0 = 1.f - wy1, wx0 = 1.f - wx1;
    int y0 = (int)y0f, x0 = (int)x0f;
    float v00 = 0.f, v01 = 0.f, v10 = 0.f, v11 = 0.f;
    bool yi0 = (y0 >= 0) & (y0 < Hh);
    bool yi1 = (y0 + 1 >= 0) & (y0 + 1 < Hh);
    bool xi0 = (x0 >= 0) & (x0 < Ww);
    bool xi1 = (x0 + 1 >= 0) & (x0 + 1 < Ww);
    if (yi0 & xi0) v00 = img[y0 * Ww + x0];
    if (yi0 & xi1) v01 = img[y0 * Ww + x0 + 1];
    if (yi1 & xi0) v10 = img[(y0 + 1) * Ww + x0];
    if (yi1 & xi1) v11 = img[(y0 + 1) * Ww + x0 + 1];
    return wy0 * wx0 * v00 + wy0 * wx1 * v01 + wy1 * wx0 * v10 + wy1 * wx1 * v11;
}

__global__ void final_k(const float* __restrict__ oa, const float* __restrict__ fusion,
                        const float* __restrict__ gk, const float* __restrict__ ascale_p,
                        float* __restrict__ out)
{
    int idx = blockIdx.x * 256 + threadIdx.x;
    if (idx >= Bb * HWp) return;
    int b = idx / HWp;
    int p = idx - b * HWp;
    int y = p / Ww;
    int x = p - y * Ww;

    float inv_as = 1.f / (ascale_p[0] + 1e-5f);

    float o[24];
    const float* ob = oa + (size_t)b * 24 * HWp + p;
#pragma unroll
    for (int c = 0; c < 24; c++) o[c] = ob[(size_t)c * HWp];

    float aff[8]; float s = 0.f;
#pragma unroll
    for (int k = 0; k < 8; k++) {
        float a = tanhf(o[16 + k]) * inv_as + gk[b * 8 + k];
        aff[k] = a;
        s += fabsf(a);
    }
    s += 1e-5f;
    s = fmaxf(s, 1.f);
    float inv = 1.f / s;
    float suma = 0.f;
#pragma unroll
    for (int k = 0; k < 8; k++) { aff[k] *= inv; suma += aff[k]; }
    float aref = 1.f - suma;

    const float* img = fusion + (size_t)b * HWp;
    float res = 0.f;
#pragma unroll
    for (int j = 0; j < 9; j++) {
        float m, dy, dx;
        if (j == 4) { m = aref; dy = 0.f; dx = 0.f; }
        else {
            int k = (j < 4) ? j : j - 1;
            m = aff[k];
            dy = o[2 * k];
            dx = o[2 * k + 1];
        }
        float ys = (float)y + (float)(j / 3 - 1) + dy;
        float xs = (float)x + (float)(j % 3 - 1) + dx;
        res += m * bilin(img, ys, xs);
    }
    out[idx] = fabsf(res);
}

// ---------------- launch ----------------
extern "C" void kernel_launch(void* const* d_in, const int* in_sizes, int n_in,
                              void* d_out, int out_size)
{
    const float* feat    = (const float*)d_in[0];
    const float* g1_w    = (const float*)d_in[1];
    const float* g1_g    = (const float*)d_in[2];
    const float* g1_b    = (const float*)d_in[3];
    const float* g2_w    = (const float*)d_in[4];
    const float* g2_g    = (const float*)d_in[5];
    const float* g2_b    = (const float*)d_in[6];
    const float* g3_w    = (const float*)d_in[7];
    const float* g3_bias = (const float*)d_in[8];
    const float* f1_w    = (const float*)d_in[9];
    const float* f1_g    = (const float*)d_in[10];
    const float* f1_b    = (const float*)d_in[11];
    const float* f2_w    = (const float*)d_in[12];
    const float* f2_bias = (const float*)d_in[13];
    const float* s1_w    = (const float*)d_in[14];
    const float* s1_b    = (const float*)d_in[15];
    const float* s2_w    = (const float*)d_in[16];
    const float* s2_b    = (const float*)d_in[17];
    const float* s3_w    = (const float*)d_in[18];
    const float* s3_b    = (const float*)d_in[19];
    const float* oa1_w   = (const float*)d_in[20];
    const float* oa1_g   = (const float*)d_in[21];
    const float* oa1_b   = (const float*)d_in[22];
    const float* oa2_w   = (const float*)d_in[23];
    const float* oa2_g   = (const float*)d_in[24];
    const float* oa2_b   = (const float*)d_in[25];
    const float* oa3_w   = (const float*)d_in[26];
    const float* oa3_bias= (const float*)d_in[27];
    const float* ascale  = (const float*)d_in[28];

    float *t1, *t1b, *t2, *guid, *fus, *t5, *oa, *part, *part2, *ss, *ss2, *pool, *gk;
    unsigned char* wp;
    cudaGetSymbolAddress((void**)&t1,   g_t1);
    cudaGetSymbolAddress((void**)&t1b,  g_t1b);
    cudaGetSymbolAddress((void**)&t2,   g_t2);
    cudaGetSymbolAddress((void**)&guid, g_guid);
    cudaGetSymbolAddress((void**)&fus,  g_fus);
    cudaGetSymbolAddress((void**)&t5,   g_t5);
    cudaGetSymbolAddress((void**)&oa,   g_oa);
    cudaGetSymbolAddress((void**)&part, g_part);
    cudaGetSymbolAddress((void**)&part2,g_part2);
    cudaGetSymbolAddress((void**)&ss,   g_ss);
    cudaGetSymbolAddress((void**)&ss2,  g_ss2);
    cudaGetSymbolAddress((void**)&pool, g_pool);
    cudaGetSymbolAddress((void**)&gk,   g_gk);
    cudaGetSymbolAddress((void**)&wp,   g_wprep);

    uint4* W_g1  = (uint4*)(wp + 0);
    uint4* W_g2  = (uint4*)(wp + 153600);
    uint4* W_g3  = (uint4*)(wp + 230400);
    uint4* W_f1  = (uint4*)(wp + 256000);
    uint4* W_f2  = (uint4*)(wp + 311296);
    uint4* W_oa1 = (uint4*)(wp + 338944);
    uint4* W_oa2 = (uint4*)(wp + 364544);
    uint4* W_oa3 = (uint4*)(wp + 415744);

    auto C1 = convmma_k<5,32,32,false,false,false>;  // g1
    auto C2 = convmma_k<5,32, 8,true ,false,false>;  // g2
    auto C3 = convmma_k<5, 8, 8,true ,true ,false>;  // g3
    auto C4 = convmma_k<3,32,32,false,false,false>;  // f1
    auto C5 = convmma_k<3,32, 1,true ,true ,true >;  // f2
    auto C6 = convmma_k<5, 8, 8,false,false,false>;  // oa1
    auto C7 = convmma_k<5, 8,24,true ,false,false>;  // oa2
    auto C8 = convmma_k<5,24,24,true ,true ,false>;  // oa3

    const int SM_c32k5 = 6*68*52*4;   // 84864
    const int SM_c8k5  = 6*68*20*4;   // 32640
    const int SM_c32k3 = 4*66*52*4;   // 54912
    const int SM_c24k5 = 6*68*44*4;   // 71808
    cudaFuncSetAttribute(C1, cudaFuncAttributeMaxDynamicSharedMemorySize, SM_c32k5);
    cudaFuncSetAttribute(C2, cudaFuncAttributeMaxDynamicSharedMemorySize, SM_c32k5);
    cudaFuncSetAttribute(C3, cudaFuncAttributeMaxDynamicSharedMemorySize, SM_c8k5);
    cudaFuncSetAttribute(C4, cudaFuncAttributeMaxDynamicSharedMemorySize, SM_c32k3);
    cudaFuncSetAttribute(C5, cudaFuncAttributeMaxDynamicSharedMemorySize, SM_c32k3);
    cudaFuncSetAttribute(C6, cudaFuncAttributeMaxDynamicSharedMemorySize, SM_c8k5);
    cudaFuncSetAttribute(C7, cudaFuncAttributeMaxDynamicSharedMemorySize, SM_c8k5);
    cudaFuncSetAttribute(C8, cudaFuncAttributeMaxDynamicSharedMemorySize, SM_c24k5);

    const dim3 blk(256);
    const dim3 cblk(128);
    const dim3 gx(5, 16, Bb);        // XT=64, YT=20

    // ---- single stream; conv at our launch index 3 for ncu capture ----
    prep_k<<<38, 256>>>(g1_w,  W_g1,  25, 32, 32);                      // 0
    prep_k<<<14, 256>>>(f1_w,  W_f1,   9, 32, 32);                      // 1
    C1<<<gx, cblk, SM_c32k5>>>(feat, W_g1, nullptr, nullptr, t1);       // 2
    C4<<<gx, cblk, SM_c32k3>>>(feat, W_f1, nullptr, nullptr, t1b);      // 3 <- ncu
    stats_k<<<dim3(32, NBLK), blk>>>(t1, part, 32);
    bnfin_k<<<32, 32>>>(part, g1_g, g1_b, 32, ss);
    prep_k<<<19, 256>>>(g2_w,  W_g2,  25, 32,  8);
    C2<<<gx, cblk, SM_c32k5>>>(t1, W_g2, nullptr, ss, t2);
    stats_k<<<dim3(8, NBLK), blk>>>(t2, part, 8);
    bnfin_k<<<8, 32>>>(part, g2_g, g2_b, 8, ss);
    prep_k<<< 7, 256>>>(g3_w,  W_g3,  25,  8,  8);
    C3<<<gx, cblk, SM_c8k5>>>(t2, W_g3, g3_bias, ss, guid);

    // fuse branch tail (f1 output in t1b)
    stats_k<<<dim3(32, NBLK), blk>>>(t1b, part2, 32);
    bnfin_k<<<32, 32>>>(part2, f1_g, f1_b, 32, ss2);
    prep_k<<< 7, 256>>>(f2_w,  W_f2,   9, 32,  1);
    C5<<<gx, cblk, SM_c32k3>>>(t1b, W_f2, f2_bias, ss2, fus);

    // sigma branch
    pool_k<<<Bb * 32, blk>>>(feat, pool);
    mlp_k<<<1, 32>>>(pool, s1_w, s1_b, s2_w, s2_b, s3_w, s3_b, gk);

    // off/aff branch (reuses t2 + part)
    prep_k<<< 7, 256>>>(oa1_w, W_oa1, 25,  8,  8);
    C6<<<gx, cblk, SM_c8k5>>>(guid, W_oa1, nullptr, nullptr, t2);
    stats_k<<<dim3(8, NBLK), blk>>>(t2, part, 8);
    bnfin_k<<<8, 32>>>(part, oa1_g, oa1_b, 8, ss);
    prep_k<<<13, 256>>>(oa2_w, W_oa2, 25,  8, 24);
    C7<<<gx, cblk, SM_c8k5>>>(t2, W_oa2, nullptr, ss, t5);
    stats_k<<<dim3(24, NBLK), blk>>>(t5, part, 24);
    bnfin_k<<<24, 32>>>(part, oa2_g, oa2_b, 24, ss);
    prep_k<<<32, 256>>>(oa3_w, W_oa3, 25, 24, 24);
    C8<<<gx, cblk, SM_c24k5>>>(t5, W_oa3, oa3_bias, ss, oa);

    // deformable gather
    final_k<<<(Bb * HWp + 255) / 256, blk>>>(oa, fus, gk, ascale, (float*)d_out);
}

// round 17
// speedup vs baseline: 1.5516x; 1.2015x over previous
#include <cuda_runtime.h>
#include <cuda_bf16.h>
#include <cstdint>

#define Hh 320
#define Ww 320
#define HWp 102400
#define Bb 8
#define NBLK 64

// ---------------- scratch (device globals: no allocation allowed) ----------------
__device__ float g_t1[(size_t)Bb*32*HWp];
__device__ float g_t1b[(size_t)Bb*32*HWp];
__device__ float g_t2[(size_t)Bb*8*HWp];
__device__ float g_guid[(size_t)Bb*8*HWp];
__device__ float g_fus[(size_t)Bb*HWp];
__device__ float g_t5[(size_t)Bb*24*HWp];
__device__ float g_oa[(size_t)Bb*24*HWp];
__device__ float g_part[32*NBLK*2];
__device__ float g_part2[32*NBLK*2];
__device__ float g_ss[64];
__device__ float g_ss2[64];
__device__ float g_pool[Bb*32];
__device__ float g_gk[Bb*8];
__device__ __align__(16) unsigned char g_wprep[544000];

// ---------------- helpers ----------------
__device__ __forceinline__ uint16_t f2bf(float v) {
    __nv_bfloat16 h = __float2bfloat16_rn(v);
    return *reinterpret_cast<uint16_t*>(&h);
}
__device__ __forceinline__ float bf2f(uint16_t b) {
    __nv_bfloat16 h = *reinterpret_cast<__nv_bfloat16*>(&b);
    return __bfloat162float(h);
}
__device__ __forceinline__ void mma16816(float* c, uint4 a, uint32_t b0, uint32_t b1) {
    asm volatile("mma.sync.aligned.m16n8k16.row.col.f32.bf16.bf16.f32 "
        "{%0,%1,%2,%3}, {%4,%5,%6,%7}, {%8,%9}, {%0,%1,%2,%3};"
        : "+f"(c[0]), "+f"(c[1]), "+f"(c[2]), "+f"(c[3])
        : "r"(a.x), "r"(a.y), "r"(a.z), "r"(a.w), "r"(b0), "r"(b1));
}

// ---------------- weight prep: pack A fragments ----------------
__global__ void prep_k(const float* __restrict__ w, uint4* __restrict__ dst,
                       int KS2, int CIN, int COUT)
{
    int CH0 = (2*CIN + 15) / 16, CH1 = (CIN + 15) / 16, NCH = CH0 + CH1;
    int MT = (COUT + 15) / 16;
    int idx = blockIdx.x * 256 + threadIdx.x;
    int total = MT * NCH * KS2 * 32;
    if (idx >= total) return;
    int lane = idx & 31;
    int rest = idx >> 5;
    int tap = rest % KS2; rest /= KS2;
    int pc = rest % NCH;
    int mt = rest / NCH;
    int g = lane >> 2, t = lane & 3;
    uint32_t av[4];
    for (int h = 0; h < 2; h++) {
        for (int mr = 0; mr < 2; mr++) {
            int m = mt * 16 + g + mr * 8;
            uint32_t pk = 0;
            if (pc < CH0) {
                int ci = pc * 8 + t + 4 * h;
                float v = (m < COUT && ci < CIN) ? w[(size_t)(m * CIN + ci) * KS2 + tap] : 0.f;
                uint16_t hb = f2bf(v);
                pk = (uint32_t)hb | ((uint32_t)hb << 16);
            } else {
                int j = (pc - CH0) * 8 + t + 4 * h;
                int ci0 = 2 * j, ci1 = 2 * j + 1;
                uint16_t l0 = 0, l1 = 0;
                if (m < COUT && ci0 < CIN) {
                    float v = w[(size_t)(m * CIN + ci0) * KS2 + tap];
                    l0 = f2bf(v - bf2f(f2bf(v)));
                }
                if (m < COUT && ci1 < CIN) {
                    float v = w[(size_t)(m * CIN + ci1) * KS2 + tap];
                    l1 = f2bf(v - bf2f(f2bf(v)));
                }
                pk = (uint32_t)l0 | ((uint32_t)l1 << 16);
            }
            av[h * 2 + mr] = pk;
        }
    }
    dst[idx] = make_uint4(av[0], av[1], av[2], av[3]);
}

// ---------------- per-pixel B builder ----------------
template<bool IN_BN, int CIN, int KPW, int CH0, int CH1>
__device__ __forceinline__ void build_px(uint32_t* __restrict__ rp,
                                         const float* __restrict__ src,
                                         bool ok, const float* __restrict__ sss)
{
    uint16_t xhb[CIN];
#pragma unroll
    for (int ci = 0; ci < CIN; ci++) {
        float v = 0.f;
        if (ok) {
            v = __ldg(src + (size_t)ci * HWp);
            if (IN_BN) v = fmaxf(fmaf(v, sss[ci], sss[CIN + ci]), 0.f);
        }
        uint16_t hb = f2bf(v);
        uint16_t lb = f2bf(v - bf2f(hb));
        int j = ci & 7;
        rp[(ci >> 3) * 8 + 2 * (j & 3) + (j >> 2)] = (uint32_t)hb | ((uint32_t)lb << 16);
        xhb[ci] = hb;
    }
#pragma unroll
    for (int j = 0; j < CIN / 2; j++) {
        int jj = j & 7;
        rp[CH0 * 8 + (j >> 3) * 8 + 2 * (jj & 3) + (jj >> 2)] =
            (uint32_t)xhb[2 * j] | ((uint32_t)xhb[2 * j + 1] << 16);
    }
#pragma unroll
    for (int j = CIN / 2; j < CH1 * 8; j++) {
        int jj = j & 7;
        rp[CH0 * 8 + (j >> 3) * 8 + 2 * (jj & 3) + (jj >> 2)] = 0;
    }
}

// ---------------- mma.sync implicit-GEMM conv (R10/v4 + XT template knob) ----------------
template<int KS, int CIN, int COUT, int XT, bool IN_BN, bool HAS_BIAS, bool TANH_OUT>
__global__ __launch_bounds__(128) void convmma_k(
    const float* __restrict__ in, const uint4* __restrict__ wfrag,
    const float* __restrict__ bias, const float* __restrict__ ssg,
    float* __restrict__ out)
{
    constexpr int PAD = KS / 2;
    constexpr int RING = KS + 1;
    constexpr int NPB = XT + KS - 1;
    constexpr int CH0 = (2 * CIN + 15) / 16;
    constexpr int CH1 = (CIN + 15) / 16;
    constexpr int NCH = CH0 + CH1;
    constexpr int KPW = NCH * 8 + 4;          // ≡ 4 (mod 8) -> conflict-free B loads
    constexpr int TAPS = KS * KS;
    constexpr int YT = 20;
    constexpr int MT = (COUT + 15) / 16;
    constexpr int NSUB = XT / 32;             // n-subtiles of 8 px per warp (2 for XT=64)

    extern __shared__ uint32_t ring[];
    __shared__ float sss[64];

    const int tid = threadIdx.x;
    const int w = tid >> 5, lane = tid & 31;
    const int g = lane >> 2, t = lane & 3;
    const int x0 = blockIdx.x * XT;
    const int yS = blockIdx.y * YT;
    const int b = blockIdx.z;

    if (IN_BN && tid < 2 * CIN) sss[tid] = ssg[tid];
    __syncthreads();

    auto build = [&](int yin) {
        int slot = (yin + PAD) % RING;
        if (tid < NPB) {
            int gx = x0 - PAD + tid;
            bool ok = (yin >= 0) & (yin < Hh) & (gx >= 0) & (gx < Ww);
            const float* src = in + (size_t)b * CIN * HWp + (ptrdiff_t)yin * Ww + gx;
            build_px<IN_BN, CIN, KPW, CH0, CH1>(
                ring + (size_t)slot * NPB * KPW + tid * KPW, src, ok, sss);
        }
    };

    const int pxb = w * (XT / 4);             // 16 px (XT64) or 8 px (XT32) per warp

    for (int j = 0; j < KS - 1; j++) build(yS - PAD + j);
    __syncthreads();

    for (int i = 0; i < YT; i += 2) {
        const int y = yS + i;
        build(y + PAD);
        build(y + PAD + 1);
        __syncthreads();

        float c[2][NSUB][MT][4];
#pragma unroll
        for (int r = 0; r < 2; r++)
#pragma unroll
            for (int n = 0; n < NSUB; n++)
#pragma unroll
                for (int mt = 0; mt < MT; mt++)
#pragma unroll
                    for (int q = 0; q < 4; q++) c[r][n][mt][q] = 0.f;

        for (int ky = 0; ky < KS; ky++) {
            const uint32_t* r0 = ring + (size_t)((y + ky) % RING) * NPB * KPW;
            const uint32_t* r1 = ring + (size_t)((y + 1 + ky) % RING) * NPB * KPW;
#pragma unroll
            for (int kx = 0; kx < KS; kx++) {
                const uint32_t* b0p = r0 + (pxb + g + kx) * KPW;
                const uint32_t* b1p = r1 + (pxb + g + kx) * KPW;
                const uint4* ap = wfrag + (size_t)(ky * KS + kx) * 32 + lane;

                uint2 qb[2][2][NSUB];          // [buf][row][n]
                uint4 ab[2][MT];
                {
                    int wo = 2 * t;
#pragma unroll
                    for (int n = 0; n < NSUB; n++) {
                        qb[0][0][n] = *(const uint2*)&b0p[wo + n * 8 * KPW];
                        qb[0][1][n] = *(const uint2*)&b1p[wo + n * 8 * KPW];
                    }
#pragma unroll
                    for (int mt = 0; mt < MT; mt++)
                        ab[0][mt] = __ldg(ap + (size_t)(mt * NCH) * TAPS * 32);
                }
#pragma unroll
                for (int pc = 0; pc < NCH; pc++) {
                    const int cur = pc & 1, nxt = cur ^ 1;
                    if (pc + 1 < NCH) {
                        int wo = (pc + 1) * 8 + 2 * t;
#pragma unroll
                        for (int n = 0; n < NSUB; n++) {
                            qb[nxt][0][n] = *(const uint2*)&b0p[wo + n * 8 * KPW];
                            qb[nxt][1][n] = *(const uint2*)&b1p[wo + n * 8 * KPW];
                        }
#pragma unroll
                        for (int mt = 0; mt < MT; mt++)
                            ab[nxt][mt] = __ldg(ap + (size_t)(mt * NCH + pc + 1) * TAPS * 32);
                    }
#pragma unroll
                    for (int mt = 0; mt < MT; mt++)
#pragma unroll
                        for (int n = 0; n < NSUB; n++) {
                            mma16816(c[0][n][mt], ab[cur][mt], qb[cur][0][n].x, qb[cur][0][n].y);
                            mma16816(c[1][n][mt], ab[cur][mt], qb[cur][1][n].x, qb[cur][1][n].y);
                        }
                }
            }
        }

#pragma unroll
        for (int r = 0; r < 2; r++) {
            int yr = y + r;
#pragma unroll
            for (int n = 0; n < NSUB; n++) {
                int xo = x0 + pxb + n * 8 + 2 * t;
                if (xo < Ww) {
#pragma unroll
                    for (int mt = 0; mt < MT; mt++) {
#pragma unroll
                        for (int h2 = 0; h2 < 2; h2++) {
                            int co = mt * 16 + g + h2 * 8;
                            if (co < COUT) {
                                float v0 = c[r][n][mt][2 * h2], v1 = c[r][n][mt][2 * h2 + 1];
                                if (HAS_BIAS) { float bv = __ldg(&bias[co]); v0 += bv; v1 += bv; }
                                if (TANH_OUT) { v0 = tanhf(v0); v1 = tanhf(v1); }
                                float2 o2 = make_float2(v0, v1);
                                *(float2*)&out[((size_t)(b * COUT + co)) * HWp + (size_t)yr * Ww + xo] = o2;
                            }
                        }
                    }
                }
            }
        }
        __syncthreads();
    }
}

// ---------------- BN stats (deterministic, no atomics) ----------------
__global__ void stats_k(const float* __restrict__ x, float* __restrict__ part, int C)
{
    const int c = blockIdx.x, blk = blockIdx.y, NB = gridDim.y;
    const int tid = threadIdx.x;
    float s = 0.f, q = 0.f;
    for (int b = 0; b < Bb; b++) {
        const float* p = x + ((size_t)(b * C + c)) * HWp;
        for (int i = blk * 256 + tid; i < HWp; i += NB * 256) {
            float v = p[i]; s += v; q += v * v;
        }
    }
    __shared__ float rs[256], rq[256];
    rs[tid] = s; rq[tid] = q; __syncthreads();
    for (int off = 128; off > 0; off >>= 1) {
        if (tid < off) { rs[tid] += rs[tid + off]; rq[tid] += rq[tid + off]; }
        __syncthreads();
    }
    if (tid == 0) {
        part[(c * NB + blk) * 2]     = rs[0];
        part[(c * NB + blk) * 2 + 1] = rq[0];
    }
}

// parallel BN finalize: one warp per channel (blockIdx.x = channel)
__global__ __launch_bounds__(32) void bnfin_k(
    const float* __restrict__ part, const float* __restrict__ gamma,
    const float* __restrict__ beta, int C, float* __restrict__ ss)
{
    int c = blockIdx.x;
    if (c >= C) return;
    int lane = threadIdx.x;
    double s = 0.0, q = 0.0;
    for (int i = lane; i < NBLK; i += 32) {
        s += part[(c * NBLK + i) * 2];
        q += part[(c * NBLK + i) * 2 + 1];
    }
#pragma unroll
    for (int o = 16; o > 0; o >>= 1) {
        s += __shfl_down_sync(0xffffffffu, s, o);
        q += __shfl_down_sync(0xffffffffu, q, o);
    }
    if (lane == 0) {
        const double N = (double)Bb * HWp;
        float mean = (float)(s / N);
        float var  = (float)(q / N) - mean * mean;
        float scl = gamma[c] * rsqrtf(var + 1e-5f);
        ss[c]     = scl;
        ss[C + c] = beta[c] - mean * scl;
    }
}

// ---------------- pool ----------------
__global__ void pool_k(const float* __restrict__ feat, float* __restrict__ p)
{
    const int bc = blockIdx.x;
    const int tid = threadIdx.x;
    const float* src = feat + (size_t)bc * HWp;
    float s = 0.f;
    for (int i = tid; i < HWp; i += 256) s += src[i];
    __shared__ float rs[256];
    rs[tid] = s; __syncthreads();
    for (int off = 128; off > 0; off >>= 1) {
        if (tid < off) rs[tid] += rs[tid + off];
        __syncthreads();
    }
    if (tid == 0) p[bc] = rs[0] * (1.f / (float)HWp);
}

// ---------------- sigma MLP + gaussian window ----------------
__device__ __forceinline__ float celu1(float x) { return x > 0.f ? x : expm1f(x); }

__global__ void mlp_k(const float* __restrict__ p,
                      const float* __restrict__ s1w, const float* __restrict__ s1b,
                      const float* __restrict__ s2w, const float* __restrict__ s2b,
                      const float* __restrict__ s3w, const float* __restrict__ s3b,
                      float* __restrict__ gk)
{
    int b = threadIdx.x;
    if (b >= Bb) return;
    float h1[16];
#pragma unroll
    for (int j = 0; j < 16; j++) {
        float a = s1b[j];
        for (int i = 0; i < 32; i++) a += p[b * 32 + i] * s1w[j * 32 + i];
        h1[j] = celu1(a);
    }
    float h2[16];
#pragma unroll
    for (int j = 0; j < 16; j++) {
        float a = s2b[j];
        for (int i = 0; i < 16; i++) a += h1[i] * s2w[j * 16 + i];
        h2[j] = celu1(a);
    }
    float sg = s3b[0];
    for (int i = 0; i < 16; i++) sg += h2[i] * s3w[i];
    sg = fmaxf(sg, 0.f) + 0.001f;
    sg += 0.2f;
    float e = expf(-1.f / (2.f * sg * sg));
    float d = 2.f * e + 1.f;
    float e1 = e / d, e0 = 1.f / d;
    float w00 = e1 * e1, w01 = e1 * e0;
    gk[b * 8 + 0] = w00; gk[b * 8 + 1] = w01; gk[b * 8 + 2] = w00; gk[b * 8 + 3] = w01;
    gk[b * 8 + 4] = w01; gk[b * 8 + 5] = w00; gk[b * 8 + 6] = w01; gk[b * 8 + 7] = w00;
}

// ---------------- final: affinity normalize + deform conv 1x9 + abs ----------------
__device__ __forceinline__ float bilin(const float* __restrict__ img, float ys, float xs)
{
    float y0f = floorf(ys), x0f = floorf(xs);
    float wy1 = ys - y0f, wx1 = xs - x0f;
    float wy0 = 1.f - wy1, wx0 = 1.f - wx1;
    int y0 = (int)y0f, x0 = (int)x0f;
    float v00 = 0.f, v01 = 0.f, v10 = 0.f, v11 = 0.f;
    bool yi0 = (y0 >= 0) & (y0 < Hh);
    bool yi1 = (y0 + 1 >= 0) & (y0 + 1 < Hh);
    bool xi0 = (x0 >= 0) & (x0 < Ww);
    bool xi1 = (x0 + 1 >= 0) & (x0 + 1 < Ww);
    if (yi0 & xi0) v00 = img[y0 * Ww + x0];
    if (yi0 & xi1) v01 = img[y0 * Ww + x0 + 1];
    if (yi1 & xi0) v10 = img[(y0 + 1) * Ww + x0];
    if (yi1 & xi1) v11 = img[(y0 + 1) * Ww + x0 + 1];
    return wy0 * wx0 * v00 + wy0 * wx1 * v01 + wy1 * wx0 * v10 + wy1 * wx1 * v11;
}

__global__ void final_k(const float* __restrict__ oa, const float* __restrict__ fusion,
                        const float* __restrict__ gk, const float* __restrict__ ascale_p,
                        float* __restrict__ out)
{
    int idx = blockIdx.x * 256 + threadIdx.x;
    if (idx >= Bb * HWp) return;
    int b = idx / HWp;
    int p = idx - b * HWp;
    int y = p / Ww;
    int x = p - y * Ww;

    float inv_as = 1.f / (ascale_p[0] + 1e-5f);

    float o[24];
    const float* ob = oa + (size_t)b * 24 * HWp + p;
#pragma unroll
    for (int c = 0; c < 24; c++) o[c] = ob[(size_t)c * HWp];

    float aff[8]; float s = 0.f;
#pragma unroll
    for (int k = 0; k < 8; k++) {
        float a = tanhf(o[16 + k]) * inv_as + gk[b * 8 + k];
        aff[k] = a;
        s += fabsf(a);
    }
    s += 1e-5f;
    s = fmaxf(s, 1.f);
    float inv = 1.f / s;
    float suma = 0.f;
#pragma unroll
    for (int k = 0; k < 8; k++) { aff[k] *= inv; suma += aff[k]; }
    float aref = 1.f - suma;

    const float* img = fusion + (size_t)b * HWp;
    float res = 0.f;
#pragma unroll
    for (int j = 0; j < 9; j++) {
        float m, dy, dx;
        if (j == 4) { m = aref; dy = 0.f; dx = 0.f; }
        else {
            int k = (j < 4) ? j : j - 1;
            m = aff[k];
            dy = o[2 * k];
            dx = o[2 * k + 1];
        }
        float ys = (float)y + (float)(j / 3 - 1) + dy;
        float xs = (float)x + (float)(j % 3 - 1) + dx;
        res += m * bilin(img, ys, xs);
    }
    out[idx] = fabsf(res);
}

// ---------------- launch ----------------
extern "C" void kernel_launch(void* const* d_in, const int* in_sizes, int n_in,
                              void* d_out, int out_size)
{
    const float* feat    = (const float*)d_in[0];
    const float* g1_w    = (const float*)d_in[1];
    const float* g1_g    = (const float*)d_in[2];
    const float* g1_b    = (const float*)d_in[3];
    const float* g2_w    = (const float*)d_in[4];
    const float* g2_g    = (const float*)d_in[5];
    const float* g2_b    = (const float*)d_in[6];
    const float* g3_w    = (const float*)d_in[7];
    const float* g3_bias = (const float*)d_in[8];
    const float* f1_w    = (const float*)d_in[9];
    const float* f1_g    = (const float*)d_in[10];
    const float* f1_b    = (const float*)d_in[11];
    const float* f2_w    = (const float*)d_in[12];
    const float* f2_bias = (const float*)d_in[13];
    const float* s1_w    = (const float*)d_in[14];
    const float* s1_b    = (const float*)d_in[15];
    const float* s2_w    = (const float*)d_in[16];
    const float* s2_b    = (const float*)d_in[17];
    const float* s3_w    = (const float*)d_in[18];
    const float* s3_b    = (const float*)d_in[19];
    const float* oa1_w   = (const float*)d_in[20];
    const float* oa1_g   = (const float*)d_in[21];
    const float* oa1_b   = (const float*)d_in[22];
    const float* oa2_w   = (const float*)d_in[23];
    const float* oa2_g   = (const float*)d_in[24];
    const float* oa2_b   = (const float*)d_in[25];
    const float* oa3_w   = (const float*)d_in[26];
    const float* oa3_bias= (const float*)d_in[27];
    const float* ascale  = (const float*)d_in[28];

    float *t1, *t1b, *t2, *guid, *fus, *t5, *oa, *part, *part2, *ss, *ss2, *pool, *gk;
    unsigned char* wp;
    cudaGetSymbolAddress((void**)&t1,   g_t1);
    cudaGetSymbolAddress((void**)&t1b,  g_t1b);
    cudaGetSymbolAddress((void**)&t2,   g_t2);
    cudaGetSymbolAddress((void**)&guid, g_guid);
    cudaGetSymbolAddress((void**)&fus,  g_fus);
    cudaGetSymbolAddress((void**)&t5,   g_t5);
    cudaGetSymbolAddress((void**)&oa,   g_oa);
    cudaGetSymbolAddress((void**)&part, g_part);
    cudaGetSymbolAddress((void**)&part2,g_part2);
    cudaGetSymbolAddress((void**)&ss,   g_ss);
    cudaGetSymbolAddress((void**)&ss2,  g_ss2);
    cudaGetSymbolAddress((void**)&pool, g_pool);
    cudaGetSymbolAddress((void**)&gk,   g_gk);
    cudaGetSymbolAddress((void**)&wp,   g_wprep);

    uint4* W_g1  = (uint4*)(wp + 0);
    uint4* W_g2  = (uint4*)(wp + 153600);
    uint4* W_g3  = (uint4*)(wp + 230400);
    uint4* W_f1  = (uint4*)(wp + 256000);
    uint4* W_f2  = (uint4*)(wp + 311296);
    uint4* W_oa1 = (uint4*)(wp + 338944);
    uint4* W_oa2 = (uint4*)(wp + 364544);
    uint4* W_oa3 = (uint4*)(wp + 415744);

    // <KS,CIN,COUT,XT,...>  XT=32 for the occupancy-starved layers
    auto C1 = convmma_k<5,32,32,32,false,false,false>;  // g1  (44.9KB -> 5 CTAs)
    auto C2 = convmma_k<5,32, 8,32,true ,false,false>;  // g2  (44.9KB -> 5 CTAs)
    auto C3 = convmma_k<5, 8, 8,64,true ,true ,false>;  // g3
    auto C4 = convmma_k<3,32,32,64,false,false,false>;  // f1
    auto C5 = convmma_k<3,32, 1,64,true ,true ,true >;  // f2
    auto C6 = convmma_k<5, 8, 8,64,false,false,false>;  // oa1
    auto C7 = convmma_k<5, 8,24,64,true ,false,false>;  // oa2
    auto C8 = convmma_k<5,24,24,32,true ,true ,false>;  // oa3 (38.0KB -> 6 CTAs)

    const int SM_g12  = 6*36*52*4;   // 44928 (g1,g2 XT32)
    const int SM_c8k5 = 6*68*20*4;   // 32640 (g3,oa1,oa2)
    const int SM_c32k3= 4*66*52*4;   // 54912 (f1,f2)
    const int SM_oa3  = 6*36*44*4;   // 38016 (oa3 XT32)
    cudaFuncSetAttribute(C1, cudaFuncAttributeMaxDynamicSharedMemorySize, SM_g12);
    cudaFuncSetAttribute(C2, cudaFuncAttributeMaxDynamicSharedMemorySize, SM_g12);
    cudaFuncSetAttribute(C3, cudaFuncAttributeMaxDynamicSharedMemorySize, SM_c8k5);
    cudaFuncSetAttribute(C4, cudaFuncAttributeMaxDynamicSharedMemorySize, SM_c32k3);
    cudaFuncSetAttribute(C5, cudaFuncAttributeMaxDynamicSharedMemorySize, SM_c32k3);
    cudaFuncSetAttribute(C6, cudaFuncAttributeMaxDynamicSharedMemorySize, SM_c8k5);
    cudaFuncSetAttribute(C7, cudaFuncAttributeMaxDynamicSharedMemorySize, SM_c8k5);
    cudaFuncSetAttribute(C8, cudaFuncAttributeMaxDynamicSharedMemorySize, SM_oa3);

    const dim3 blk(256);
    const dim3 cblk(128);
    const dim3 gx64(5, 16, Bb);      // XT=64
    const dim3 gx32(10, 16, Bb);     // XT=32

    // ---- single stream; conv at our launch index 3 for ncu capture ----
    prep_k<<<38, 256>>>(g1_w,  W_g1,  25, 32, 32);                      // 0
    prep_k<<<14, 256>>>(f1_w,  W_f1,   9, 32, 32);                      // 1
    C1<<<gx32, cblk, SM_g12>>>(feat, W_g1, nullptr, nullptr, t1);       // 2
    C4<<<gx64, cblk, SM_c32k3>>>(feat, W_f1, nullptr, nullptr, t1b);    // 3 <- ncu
    stats_k<<<dim3(32, NBLK), blk>>>(t1, part, 32);
    bnfin_k<<<32, 32>>>(part, g1_g, g1_b, 32, ss);
    prep_k<<<19, 256>>>(g2_w,  W_g2,  25, 32,  8);
    C2<<<gx32, cblk, SM_g12>>>(t1, W_g2, nullptr, ss, t2);
    stats_k<<<dim3(8, NBLK), blk>>>(t2, part, 8);
    bnfin_k<<<8, 32>>>(part, g2_g, g2_b, 8, ss);
    prep_k<<< 7, 256>>>(g3_w,  W_g3,  25,  8,  8);
    C3<<<gx64, cblk, SM_c8k5>>>(t2, W_g3, g3_bias, ss, guid);

    // fuse branch tail (f1 output in t1b)
    stats_k<<<dim3(32, NBLK), blk>>>(t1b, part2, 32);
    bnfin_k<<<32, 32>>>(part2, f1_g, f1_b, 32, ss2);
    prep_k<<< 7, 256>>>(f2_w,  W_f2,   9, 32,  1);
    C5<<<gx64, cblk, SM_c32k3>>>(t1b, W_f2, f2_bias, ss2, fus);

    // sigma branch
    pool_k<<<Bb * 32, blk>>>(feat, pool);
    mlp_k<<<1, 32>>>(pool, s1_w, s1_b, s2_w, s2_b, s3_w, s3_b, gk);

    // off/aff branch (reuses t2 + part)
    prep_k<<< 7, 256>>>(oa1_w, W_oa1, 25,  8,  8);
    C6<<<gx64, cblk, SM_c8k5>>>(guid, W_oa1, nullptr, nullptr, t2);
    stats_k<<<dim3(8, NBLK), blk>>>(t2, part, 8);
    bnfin_k<<<8, 32>>>(part, oa1_g, oa1_b, 8, ss);
    prep_k<<<13, 256>>>(oa2_w, W_oa2, 25,  8, 24);
    C7<<<gx64, cblk, SM_c8k5>>>(t2, W_oa2, nullptr, ss, t5);
    stats_k<<<dim3(24, NBLK), blk>>>(t5, part, 24);
    bnfin_k<<<24, 32>>>(part, oa2_g, oa2_b, 24, ss);
    prep_k<<<32, 256>>>(oa3_w, W_oa3, 25, 24, 24);
    C8<<<gx32, cblk, SM_oa3>>>(t5, W_oa3, oa3_bias, ss, oa);

    // deformable gather
    final_k<<<(Bb * HWp + 255) / 256, blk>>>(oa, fus, gk, ascale, (float*)d_out);
}